// round 10
// baseline (speedup 1.0000x reference)
#include <cuda_runtime.h>
#include <cuda_fp16.h>
#include <cstdint>

#define NB 32768
#define NK 8192
#define ND 256
#define BETA 0.25f
#define CAP 32
#define EMAXF (1.0f / 8192.0f)

// ---- global scratch ----
__device__ float g_znorm[NB];
__device__ float g_enorm[NK];
__device__ int   g_idx[NB];
__device__ float g_partial[NB];
__device__ float g_zwin[NB];
__device__ __align__(16) __half g_zT[(size_t)ND * NB];   // [dim][row] fp16
__device__ __align__(16) __half g_eT[(size_t)ND * NK];   // [dim][code] fp16
__device__ int   g_cand[(size_t)NB * CAP];
__device__ int   g_cnt[NB];

// ---------------------------------------------------------------------------
// Row squared-norms (exact fp32).
// ---------------------------------------------------------------------------
__global__ void vq_rownorm_kernel(const float* __restrict__ x, int nrows, int which) {
    int gw   = (int)((blockIdx.x * (unsigned)blockDim.x + threadIdx.x) >> 5);
    int lane = threadIdx.x & 31;
    if (gw >= nrows) return;
    const float4* row = (const float4*)(x + (size_t)gw * ND);
    float4 v0 = row[lane];
    float4 v1 = row[lane + 32];
    float s = v0.x * v0.x + v0.y * v0.y + v0.z * v0.z + v0.w * v0.w
            + v1.x * v1.x + v1.y * v1.y + v1.z * v1.z + v1.w * v1.w;
#pragma unroll
    for (int off = 16; off > 0; off >>= 1) s += __shfl_down_sync(0xffffffffu, s, off);
    if (lane == 0) { if (which) g_enorm[gw] = s; else g_znorm[gw] = s; }
}

// ---------------------------------------------------------------------------
// z -> fp16 transposed [dim][row] + per-row provable window.
// Block = 32 rows; warp handles 4 rows; then 256 threads transpose via smem.
// ---------------------------------------------------------------------------
__global__ void vq_quantz_kernel(const float* __restrict__ z) {
    __shared__ __half zsm[32][256];
    int tid = threadIdx.x, w = tid >> 5, lane = tid & 31;
    int rbase = blockIdx.x * 32;
#pragma unroll
    for (int rr = 0; rr < 4; rr++) {
        int row = rbase + w * 4 + rr;
        const float4* rp = (const float4*)(z + (size_t)row * ND);
        float4 a = rp[lane * 2], b = rp[lane * 2 + 1];
        float v[8] = {a.x, a.y, a.z, a.w, b.x, b.y, b.z, b.w};
        union { __half h[8]; int4 v4; } u;
        float err = 0.0f, saz = 0.0f;
#pragma unroll
        for (int i = 0; i < 8; i++) {
            u.h[i] = __float2half_rn(v[i]);
            err += fabsf(v[i] - __half2float(u.h[i]));
            saz += fabsf(v[i]);
        }
        *(int4*)&zsm[w * 4 + rr][lane * 8] = u.v4;
#pragma unroll
        for (int off = 16; off > 0; off >>= 1) {
            err += __shfl_down_sync(0xffffffffu, err, off);
            saz += __shfl_down_sync(0xffffffffu, saz, off);
        }
        if (lane == 0) {
            // B >= |dot - fp16_twolevel_dot|: z-quant + e-quant + product/acc rounding
            float B = EMAXF * err + saz * (1.25e-7f + 34.0f * EMAXF * 4.883e-4f) + 1.2e-5f;
            g_zwin[row] = 4.0f * B * 1.05f + 3.2e-4f;
        }
    }
    __syncthreads();
    // transpose: thread tid = dim, write 32 consecutive rows
    ushort tmp[32];
#pragma unroll
    for (int r = 0; r < 32; r++) tmp[r] = __half_as_ushort(zsm[r][tid]);
    int4* dst = (int4*)&g_zT[(size_t)tid * NB + rbase];
#pragma unroll
    for (int q = 0; q < 4; q++) dst[q] = ((int4*)tmp)[q];
}

// ---------------------------------------------------------------------------
// e -> fp16 transposed [dim][code].
// ---------------------------------------------------------------------------
__global__ void vq_quante_kernel(const float* __restrict__ e) {
    __shared__ __half esm[32][256];
    int tid = threadIdx.x, w = tid >> 5, lane = tid & 31;
    int cbase = blockIdx.x * 32;
#pragma unroll
    for (int rr = 0; rr < 4; rr++) {
        int code = cbase + w * 4 + rr;
        const float4* rp = (const float4*)(e + (size_t)code * ND);
        float4 a = rp[lane * 2], b = rp[lane * 2 + 1];
        float v[8] = {a.x, a.y, a.z, a.w, b.x, b.y, b.z, b.w};
        union { __half h[8]; int4 v4; } u;
#pragma unroll
        for (int i = 0; i < 8; i++) u.h[i] = __float2half_rn(v[i]);
        *(int4*)&esm[w * 4 + rr][lane * 8] = u.v4;
    }
    __syncthreads();
    ushort tmp[32];
#pragma unroll
    for (int r = 0; r < 32; r++) tmp[r] = __half_as_ushort(esm[r][tid]);
    int4* dst = (int4*)&g_eT[(size_t)tid * NK + cbase];
#pragma unroll
    for (int q = 0; q < 4; q++) dst[q] = ((int4*)tmp)[q];
}

// ---------------------------------------------------------------------------
// fp16 HFMA2 filter GEMM + provable-window candidate collection (R9 scheme).
// 128 rows/CTA x 64 code tiles; 8x8 per thread as half2 pair accumulators.
// ---------------------------------------------------------------------------
__global__ __launch_bounds__(256, 2)
void vq_filter_kernel() {
    __shared__ __half zs[32 * 128];
    __shared__ __half es[32 * 128];
    __shared__ __half esw[32 * 128];
    __shared__ float bsh[128];
    __shared__ int rb[128], rc[128], rl[128 * CAP];

    const int tid = threadIdx.x;
    const int tx  = tid & 15;
    const int ty  = tid >> 4;
    const int m0  = blockIdx.x * 128;

    if (tid < 128) { rb[tid] = 0x7F800000; rc[tid] = 0; }

    float arow[8], wrow[8];
#pragma unroll
    for (int i = 0; i < 8; i++) {
        arow[i] = g_znorm[m0 + ty * 8 + i];
        wrow[i] = g_zwin[m0 + ty * 8 + i];
    }

    const __half2 hz2 = __floats2half2_rn(0.0f, 0.0f);
    __half2 sumA[4][4], sumB[4][4];
#pragma unroll
    for (int p = 0; p < 4; p++)
#pragma unroll
        for (int q = 0; q < 4; q++) { sumA[p][q] = hz2; sumB[p][q] = hz2; }

    for (int t = 0; t < 64; t++) {
        const int k0 = t * 128;
        for (int c = 0; c < 8; c++) {
            __syncthreads();   // prior compute/epilogue done; tiles reusable
#pragma unroll
            for (int i = 0; i < 2; i++) {
                int j = tid + 256 * i;           // 512 int4 = 8KB per tile
                int dim = j >> 4, seg = j & 15;  // dim 0..31, 16B-seg 0..15
                int4 zv = *(const int4*)&g_zT[(size_t)(c * 32 + dim) * NB + m0 + seg * 8];
                *(int4*)&zs[dim * 128 + seg * 8] = zv;
                int4 ev = *(const int4*)&g_eT[(size_t)(c * 32 + dim) * NK + k0 + seg * 8];
                *(int4*)&es[dim * 128 + seg * 8] = ev;
                int4 sw;
                sw.x = __byte_perm(ev.x, ev.x, 0x1032);
                sw.y = __byte_perm(ev.y, ev.y, 0x1032);
                sw.z = __byte_perm(ev.z, ev.z, 0x1032);
                sw.w = __byte_perm(ev.w, ev.w, 0x1032);
                *(int4*)&esw[dim * 128 + seg * 8] = sw;
            }
            if (c == 0 && tid < 128) bsh[tid] = g_enorm[k0 + tid];
            __syncthreads();

#pragma unroll
            for (int seg = 0; seg < 2; seg++) {
                __half2 accA[4][4], accB[4][4];
#pragma unroll
                for (int p = 0; p < 4; p++)
#pragma unroll
                    for (int q = 0; q < 4; q++) { accA[p][q] = hz2; accB[p][q] = hz2; }
#pragma unroll
                for (int dd = 0; dd < 16; dd++) {
                    int d = seg * 16 + dd;
                    int4 zraw = *(const int4*)&zs[d * 128 + ty * 8];
                    int4 eraw = *(const int4*)&es[d * 128 + tx * 8];
                    int4 wraw = *(const int4*)&esw[d * 128 + tx * 8];
                    const __half2* zp = (const __half2*)&zraw;
                    const __half2* ep = (const __half2*)&eraw;
                    const __half2* wp = (const __half2*)&wraw;
#pragma unroll
                    for (int p = 0; p < 4; p++)
#pragma unroll
                        for (int q = 0; q < 4; q++) {
                            accA[p][q] = __hfma2(zp[p], ep[q], accA[p][q]);
                            accB[p][q] = __hfma2(zp[p], wp[q], accB[p][q]);
                        }
                }
#pragma unroll
                for (int p = 0; p < 4; p++)
#pragma unroll
                    for (int q = 0; q < 4; q++) {
                        sumA[p][q] = __hadd2(sumA[p][q], accA[p][q]);
                        sumB[p][q] = __hadd2(sumB[p][q], accB[p][q]);
                    }
            }
        }

        // ---- tile epilogue: dots -> fp32 dists, running min, window append ----
        float dd2[8][8];
#pragma unroll
        for (int p = 0; p < 4; p++)
#pragma unroll
            for (int q = 0; q < 4; q++) {
                float2 fa = __half22float2(sumA[p][q]);
                float2 fb = __half22float2(sumB[p][q]);
                dd2[2 * p][2 * q]         = fa.x;
                dd2[2 * p + 1][2 * q + 1] = fa.y;
                dd2[2 * p][2 * q + 1]     = fb.x;
                dd2[2 * p + 1][2 * q]     = fb.y;
                sumA[p][q] = hz2; sumB[p][q] = hz2;
            }
#pragma unroll
        for (int i = 0; i < 8; i++) {
            float tmn = 3.4028235e38f;
#pragma unroll
            for (int j = 0; j < 8; j++)
                tmn = fminf(tmn, fmaf(-2.0f, dd2[i][j], arow[i] + bsh[tx * 8 + j]));
            atomicMin(&rb[ty * 8 + i], __float_as_int(tmn));
        }
        __syncthreads();
#pragma unroll
        for (int i = 0; i < 8; i++) {
            int lrow = ty * 8 + i;
            float lim = __int_as_float(rb[lrow]) + wrow[i];
#pragma unroll
            for (int j = 0; j < 8; j++) {
                float d = fmaf(-2.0f, dd2[i][j], arow[i] + bsh[tx * 8 + j]);
                if (d <= lim) {
                    int p = atomicAdd(&rc[lrow], 1);
                    if (p < CAP) rl[lrow * CAP + p] = k0 + tx * 8 + j;
                }
            }
        }
        // next chunk's first __syncthreads orders phase2 before tile reuse
    }
    __syncthreads();
    if (tid < 128) {
        int cnt = rc[tid];
        g_cnt[m0 + tid] = (cnt > CAP) ? -1 : cnt;
        int n = cnt > CAP ? CAP : cnt;
        for (int q = 0; q < n; q++) g_cand[(size_t)(m0 + tid) * CAP + q] = rl[tid * CAP + q];
    }
}

// ---------------------------------------------------------------------------
// Exact fp32 recheck (R9-proven): warp per row, lane per candidate.
// ---------------------------------------------------------------------------
__global__ void vq_recheck_kernel(const float* __restrict__ z, const float* __restrict__ e) {
    int row  = blockIdx.x * 8 + (threadIdx.x >> 5);
    int lane = threadIdx.x & 31;
    int n = g_cnt[row];
    if (n == 1) {
        if (lane == 0) g_idx[row] = g_cand[(size_t)row * CAP];
        return;
    }
    const float* zr = z + (size_t)row * ND;
    float a = g_znorm[row];
    float bd = 3.4028235e38f;
    int   bk = 0x7FFFFFFF;
    if (n >= 0) {
        if (lane < n) {
            int k = g_cand[(size_t)row * CAP + lane];
            const float* er = e + (size_t)k * ND;
            float dot = 0.0f;
#pragma unroll 8
            for (int d = 0; d < ND; d++) dot = fmaf(zr[d], er[d], dot);
            bd = fmaf(-2.0f, dot, a + g_enorm[k]);
            bk = k;
        }
    } else {
        for (int k = lane; k < NK; k += 32) {
            const float* er = e + (size_t)k * ND;
            float dot = 0.0f;
#pragma unroll 8
            for (int d = 0; d < ND; d++) dot = fmaf(zr[d], er[d], dot);
            float dist = fmaf(-2.0f, dot, a + g_enorm[k]);
            if (dist < bd) { bd = dist; bk = k; }
        }
    }
#pragma unroll
    for (int off = 16; off > 0; off >>= 1) {
        float od = __shfl_down_sync(0xffffffffu, bd, off);
        int   ok = __shfl_down_sync(0xffffffffu, bk, off);
        if (od < bd || (od == bd && ok < bk)) { bd = od; bk = ok; }
    }
    if (lane == 0) g_idx[row] = bk;
}

// ---------------------------------------------------------------------------
// Gather + straight-through output + per-row loss partial + index output.
// ---------------------------------------------------------------------------
__global__ void vq_gather_kernel(const float* __restrict__ z,
                                 const float* __restrict__ e,
                                 float* __restrict__ out) {
    int row = blockIdx.x;
    int t   = threadIdx.x;
    int idx = g_idx[row];
    float zv = z[(size_t)row * ND + t];
    float ev = e[(size_t)idx * ND + t];
    float d  = ev - zv;
    out[(size_t)row * ND + t] = zv + d;
    float sq = d * d;
#pragma unroll
    for (int off = 16; off > 0; off >>= 1) sq += __shfl_down_sync(0xffffffffu, sq, off);
    __shared__ float red[8];
    if ((t & 31) == 0) red[t >> 5] = sq;
    __syncthreads();
    if (t < 8) {
        float v = red[t];
#pragma unroll
        for (int off = 4; off > 0; off >>= 1) v += __shfl_down_sync(0xffu, v, off);
        if (t == 0) g_partial[row] = v;
    }
    if (t == 0) out[(size_t)NB * ND + 2 + row] = (float)idx;
}

__global__ void vq_finalize_kernel(float* __restrict__ out) {
    int t = threadIdx.x;
    float s = 0.0f;
    for (int i = t; i < NB; i += 256) s += g_partial[i];
#pragma unroll
    for (int off = 16; off > 0; off >>= 1) s += __shfl_down_sync(0xffffffffu, s, off);
    __shared__ float red[8];
    if ((t & 31) == 0) red[t >> 5] = s;
    __syncthreads();
    if (t == 0) {
        float tot = 0.0f;
#pragma unroll
        for (int w = 0; w < 8; w++) tot += red[w];
        float l = BETA * (tot / (float)((size_t)NB * ND));
        out[(size_t)NB * ND]     = l;
        out[(size_t)NB * ND + 1] = l;
    }
}

extern "C" void kernel_launch(void* const* d_in, const int* in_sizes, int n_in,
                              void* d_out, int out_size) {
    const float* z = (const float*)d_in[0];
    const float* e = (const float*)d_in[1];
    float* out = (float*)d_out;

    vq_rownorm_kernel<<<(NB * 32 + 255) / 256, 256>>>(z, NB, 0);
    vq_rownorm_kernel<<<(NK * 32 + 255) / 256, 256>>>(e, NK, 1);
    vq_quantz_kernel<<<NB / 32, 256>>>(z);
    vq_quante_kernel<<<NK / 32, 256>>>(e);
    vq_filter_kernel<<<NB / 128, 256>>>();
    vq_recheck_kernel<<<NB / 8, 256>>>(z, e);
    vq_gather_kernel<<<NB, 256>>>(z, e, out);
    vq_finalize_kernel<<<1, 256>>>(out);
}

// round 12
// speedup vs baseline: 63.3528x; 63.3528x over previous
#include <cuda_runtime.h>

#define NB 32768
#define NK 8192
#define ND 256
#define BETA 0.25f

#define BM 112                 // rows per CTA: 293 CTAs -> 145 SMs x2 + 3 x1, near-ideal makespan
#define GRID 293               // ceil(32768/112)
#define BN 128
#define BD 32
#define SLDZ (BM + 4)          // 116
#define SLDE (BN + 4)          // 132

// Scratch (no allocations allowed in kernel_launch).
__device__ float g_znorm[NB];
__device__ float g_enorm[NK];
__device__ int   g_idx[NB];
__device__ float g_partial[NB];

// ---------------------------------------------------------------------------
// Row squared-norms: one warp per row, vectorized float4 loads.
// ---------------------------------------------------------------------------
__global__ void vq_rownorm_kernel(const float* __restrict__ x, int nrows, int which) {
    int gw   = (int)((blockIdx.x * (unsigned)blockDim.x + threadIdx.x) >> 5);
    int lane = threadIdx.x & 31;
    if (gw >= nrows) return;
    const float4* row = (const float4*)(x + (size_t)gw * ND);
    float4 v0 = row[lane];
    float4 v1 = row[lane + 32];
    float s = v0.x * v0.x + v0.y * v0.y + v0.z * v0.z + v0.w * v0.w
            + v1.x * v1.x + v1.y * v1.y + v1.z * v1.z + v1.w * v1.w;
#pragma unroll
    for (int off = 16; off > 0; off >>= 1)
        s += __shfl_down_sync(0xffffffffu, s, off);
    if (lane == 0) {
        if (which) g_enorm[gw] = s;
        else       g_znorm[gw] = s;
    }
}

// ---------------------------------------------------------------------------
// Fused distance-GEMM + running argmin (R2-proven arithmetic), rebalanced to
// BM=112 x 293 CTAs so all 148 SMs carry equal work (makespan ~1.01x ideal
// instead of the 2U/1.73U = 1.16x imbalance of the 256-CTA BM=128 grid).
// dist = fmaf(-2, dot, ||z||^2 + ||e||^2); sequential-fma dot order identical
// per (row, code); ascending-k strict '<' matches jnp.argmin tie-breaking.
// Rows past NB are clamped to NB-1 (duplicate compute, writes guarded).
// ---------------------------------------------------------------------------
__global__ __launch_bounds__(256, 2)
void vq_argmin_kernel(const float* __restrict__ z, const float* __restrict__ e) {
    __shared__ float smem[BD * SLDZ + BD * SLDE + BN];   // 32.3 KB
    float* zs  = smem;                    // [dim][row]
    float* es  = smem + BD * SLDZ;        // [dim][code]
    float* bsh = smem + BD * SLDZ + BD * SLDE;

    const int tid = threadIdx.x;
    const int tx  = tid & 15;             // 8 codes
    const int ty  = tid >> 4;             // 7 rows: ty*7 .. ty*7+6
    const int m0  = blockIdx.x * BM;

    float best[7];
    int   bidx[7];
#pragma unroll
    for (int i = 0; i < 7; i++) { best[i] = 3.4028235e38f; bidx[i] = 0; }

    float arow[7];
#pragma unroll
    for (int i = 0; i < 7; i++) {
        int r = m0 + ty * 7 + i;
        arow[i] = g_znorm[r < NB ? r : NB - 1];
    }

    const int lc = tid & 31;   // d-column within chunk
    const int lr = tid >> 5;   // base row (0..7) for tile loads

    for (int k0 = 0; k0 < NK; k0 += BN) {
        if (tid < BN) bsh[tid] = g_enorm[k0 + tid];

        float acc[7][8];
#pragma unroll
        for (int i = 0; i < 7; i++)
#pragma unroll
            for (int j = 0; j < 8; j++) acc[i][j] = 0.0f;

        for (int d0 = 0; d0 < ND; d0 += BD) {
            __syncthreads();   // protect smem tiles (and bsh on first pass)
#pragma unroll
            for (int rr = 0; rr < BM; rr += 8) {
                int r = m0 + lr + rr;
                zs[lc * SLDZ + lr + rr] = z[(size_t)(r < NB ? r : NB - 1) * ND + d0 + lc];
            }
#pragma unroll
            for (int rr = 0; rr < BN; rr += 8) {
                es[lc * SLDE + lr + rr] = e[(size_t)(k0 + lr + rr) * ND + d0 + lc];
            }
            __syncthreads();
#pragma unroll 8
            for (int dd = 0; dd < BD; dd++) {
                float za[7];
#pragma unroll
                for (int i = 0; i < 7; i++) za[i] = zs[dd * SLDZ + ty * 7 + i];
                float4 eb0 = *(const float4*)&es[dd * SLDE + tx * 8];
                float4 eb1 = *(const float4*)&es[dd * SLDE + tx * 8 + 4];
                float eb[8] = {eb0.x, eb0.y, eb0.z, eb0.w, eb1.x, eb1.y, eb1.z, eb1.w};
#pragma unroll
                for (int i = 0; i < 7; i++)
#pragma unroll
                    for (int j = 0; j < 8; j++)
                        acc[i][j] = fmaf(za[i], eb[j], acc[i][j]);
            }
        }

        // Epilogue: distances + running argmin for this code tile.
#pragma unroll
        for (int i = 0; i < 7; i++) {
#pragma unroll
            for (int j = 0; j < 8; j++) {
                float dv = fmaf(-2.0f, acc[i][j], arow[i] + bsh[tx * 8 + j]);
                int   kk = k0 + tx * 8 + j;
                if (dv < best[i]) { best[i] = dv; bidx[i] = kk; }
            }
        }
        __syncthreads();   // bsh is rewritten at top of next tile
    }

    // Cross-thread reduction: 16 threads (tx) share each of the 112 rows.
    float* rval = smem;                        // BM*16 floats
    int*   ridx = (int*)(smem + BM * 16);      // BM*16 ints
#pragma unroll
    for (int i = 0; i < 7; i++) {
        rval[(ty * 7 + i) * 16 + tx] = best[i];
        ridx[(ty * 7 + i) * 16 + tx] = bidx[i];
    }
    __syncthreads();
    if (tid < BM && m0 + tid < NB) {
        float bv = rval[tid * 16];
        int   bi = ridx[tid * 16];
#pragma unroll
        for (int t = 1; t < 16; t++) {
            float v  = rval[tid * 16 + t];
            int   ix = ridx[tid * 16 + t];
            if (v < bv || (v == bv && ix < bi)) { bv = v; bi = ix; }
        }
        g_idx[m0 + tid] = bi;
    }
}

// ---------------------------------------------------------------------------
// Gather + straight-through output + per-row loss partial + index output.
// ---------------------------------------------------------------------------
__global__ void vq_gather_kernel(const float* __restrict__ z,
                                 const float* __restrict__ e,
                                 float* __restrict__ out) {
    int row = blockIdx.x;
    int t   = threadIdx.x;
    int idx = g_idx[row];

    float zv = z[(size_t)row * ND + t];
    float ev = e[(size_t)idx * ND + t];
    float d  = ev - zv;                         // fl(z_q - z)
    out[(size_t)row * ND + t] = zv + d;         // z + stopgrad(z_q - z)
    float sq = d * d;

#pragma unroll
    for (int off = 16; off > 0; off >>= 1)
        sq += __shfl_down_sync(0xffffffffu, sq, off);

    __shared__ float red[8];
    if ((t & 31) == 0) red[t >> 5] = sq;
    __syncthreads();
    if (t < 8) {
        float v = red[t];
#pragma unroll
        for (int off = 4; off > 0; off >>= 1)
            v += __shfl_down_sync(0xffu, v, off);
        if (t == 0) g_partial[row] = v;
    }
    if (t == 0) out[(size_t)NB * ND + 2 + row] = (float)idx;
}

// ---------------------------------------------------------------------------
// Final scalar reduction: sums per-row loss partials, writes both losses.
// ---------------------------------------------------------------------------
__global__ void vq_finalize_kernel(float* __restrict__ out) {
    int t = threadIdx.x;
    float s = 0.0f;
    for (int i = t; i < NB; i += 256) s += g_partial[i];
#pragma unroll
    for (int off = 16; off > 0; off >>= 1)
        s += __shfl_down_sync(0xffffffffu, s, off);
    __shared__ float red[8];
    if ((t & 31) == 0) red[t >> 5] = s;
    __syncthreads();
    if (t == 0) {
        float tot = 0.0f;
#pragma unroll
        for (int w = 0; w < 8; w++) tot += red[w];
        float l = BETA * (tot / (float)((size_t)NB * ND));
        out[(size_t)NB * ND]     = l;   // vq_loss
        out[(size_t)NB * ND + 1] = l;   // commit (numerically identical)
    }
}

extern "C" void kernel_launch(void* const* d_in, const int* in_sizes, int n_in,
                              void* d_out, int out_size) {
    const float* z = (const float*)d_in[0];
    const float* e = (const float*)d_in[1];
    float* out = (float*)d_out;

    vq_rownorm_kernel<<<(NB * 32 + 255) / 256, 256>>>(z, NB, 0);
    vq_rownorm_kernel<<<(NK * 32 + 255) / 256, 256>>>(e, NK, 1);
    vq_argmin_kernel<<<GRID, 256>>>(z, e);
    vq_gather_kernel<<<NB, 256>>>(z, e, out);
    vq_finalize_kernel<<<1, 256>>>(out);
}